// round 1
// baseline (speedup 1.0000x reference)
#include <cuda_runtime.h>
#include <cuda_bf16.h>
#include <math.h>

// Problem constants
// B=2, T=2048, DIM=2048, H=16, KV=4, D=128, G=4
#define BT 4096        // B*T rows
#define CDIM 2048
#define KVDIM 512

// Scratch (device globals; no allocation allowed)
__device__ float g_q[(size_t)BT * CDIM];
__device__ float g_k[(size_t)BT * KVDIM];
__device__ float g_v[(size_t)BT * KVDIM];
__device__ float g_att[(size_t)BT * CDIM];

// ---------------------------------------------------------------------------
// Tiled NT GEMM: C[M,N] = A[M,K] * B[N,K]^T + bias[N]
// 128x128 block, BK=8, 256 threads, 8x8 per-thread (4+4 split for
// conflict-free smem float4 loads).
// ---------------------------------------------------------------------------
__global__ __launch_bounds__(256) void gemm_nt(
    const float* __restrict__ A, const float* __restrict__ B,
    const float* __restrict__ bias, float* __restrict__ C,
    int M, int N, int K)
{
    __shared__ float As[8][128];
    __shared__ float Bs[8][128];

    const int tid = threadIdx.x;
    const int tx = tid & 15;
    const int ty = tid >> 4;
    const int bm = blockIdx.y * 128;
    const int bn = blockIdx.x * 128;

    const int lr = tid >> 1;          // 0..127
    const int lc = (tid & 1) * 4;     // 0 or 4

    const float* Ap = A + (size_t)(bm + lr) * K + lc;
    const float* Bp = B + (size_t)(bn + lr) * K + lc;

    float acc[8][8];
#pragma unroll
    for (int i = 0; i < 8; i++)
#pragma unroll
        for (int j = 0; j < 8; j++) acc[i][j] = 0.0f;

    for (int k0 = 0; k0 < K; k0 += 8) {
        float4 a4 = *(const float4*)(Ap + k0);
        float4 b4 = *(const float4*)(Bp + k0);
        __syncthreads();
        As[lc + 0][lr] = a4.x; As[lc + 1][lr] = a4.y;
        As[lc + 2][lr] = a4.z; As[lc + 3][lr] = a4.w;
        Bs[lc + 0][lr] = b4.x; Bs[lc + 1][lr] = b4.y;
        Bs[lc + 2][lr] = b4.z; Bs[lc + 3][lr] = b4.w;
        __syncthreads();
#pragma unroll
        for (int kk = 0; kk < 8; kk++) {
            float a[8], b[8];
            *(float4*)(a)     = *(const float4*)&As[kk][ty * 4];
            *(float4*)(a + 4) = *(const float4*)&As[kk][64 + ty * 4];
            *(float4*)(b)     = *(const float4*)&Bs[kk][tx * 4];
            *(float4*)(b + 4) = *(const float4*)&Bs[kk][64 + tx * 4];
#pragma unroll
            for (int i = 0; i < 8; i++)
#pragma unroll
                for (int j = 0; j < 8; j++)
                    acc[i][j] += a[i] * b[j];
        }
    }

    // epilogue: two float4 stores per row-half
#pragma unroll
    for (int i = 0; i < 8; i++) {
        int row = bm + ((i < 4) ? (ty * 4 + i) : (64 + ty * 4 + (i - 4)));
        int c0 = bn + tx * 4;
        int c1 = bn + 64 + tx * 4;
        float4 o0, o1;
        o0.x = acc[i][0] + bias[c0 + 0];
        o0.y = acc[i][1] + bias[c0 + 1];
        o0.z = acc[i][2] + bias[c0 + 2];
        o0.w = acc[i][3] + bias[c0 + 3];
        o1.x = acc[i][4] + bias[c1 + 0];
        o1.y = acc[i][5] + bias[c1 + 1];
        o1.z = acc[i][6] + bias[c1 + 2];
        o1.w = acc[i][7] + bias[c1 + 3];
        *(float4*)(C + (size_t)row * N + c0) = o0;
        *(float4*)(C + (size_t)row * N + c1) = o1;
    }
}

// ---------------------------------------------------------------------------
// RoPE as the reference actually computes it: the angle index is the HEAD
// index (reference slices cos[..., :H, :] over the position axis and
// broadcasts over (b, t)).  data layout: [row(=b*T+t)][heads*128]
// ---------------------------------------------------------------------------
__global__ void rope_kernel(float* __restrict__ data, int heads)
{
    int idx = blockIdx.x * blockDim.x + threadIdx.x;
    int total = BT * heads * 64;
    if (idx >= total) return;
    int d = idx & 63;
    int h = (idx >> 6) % heads;
    int row = idx / (heads * 64);

    float invf = powf(10000.0f, -(float)d / 64.0f);  // 1/10000^(2d/128)
    float ang = (float)h * invf;
    float c = cosf(ang);
    float s = sinf(ang);

    float* p = data + (size_t)row * heads * 128 + h * 128;
    float x1 = p[d];
    float x2 = p[d + 64];
    p[d]      = x1 * c - x2 * s;   // x*cos + (-x2)*sin
    p[d + 64] = x2 * c + x1 * s;   // x*cos + ( x1)*sin
}

// ---------------------------------------------------------------------------
// Flash-style attention with the reference's ADDITIVE mask (scores + 1.0 where
// s<=t, softmax over all 2048 keys).
// Br=Bc=64, Dh=128.  Q and K tiles stored d-major (transposed) for
// conflict-free float4 smem reads in the S-GEMM; V stored row-major in the
// same buffer as K (sequential reuse).  Online softmax, O in registers.
// grid = (T/64, B*KV*G), block = 256 (16x16).
// ---------------------------------------------------------------------------
#define QK_LD 68   // 64 + 4 pad (16B-aligned row stride: 272B)
#define PS_LD 68

__global__ __launch_bounds__(256) void attn_kernel(
    const float* __restrict__ q, const float* __restrict__ k,
    const float* __restrict__ v, float* __restrict__ o)
{
    extern __shared__ float sm[];
    float* Qs = sm;                        // [128][QK_LD] transposed, pre-scaled
    float* KV = sm + 128 * QK_LD;          // K: [128][QK_LD] transp / V: [64][128]
    float* Ps = sm + 2 * 128 * QK_LD;      // [64][PS_LD]

    const int tid = threadIdx.x;
    const int tx = tid & 15;
    const int ty = tid >> 4;
    const int t0 = blockIdx.x * 64;
    const int bh = blockIdx.y;             // b*16 + kv*4 + g
    const int b = bh >> 4;
    const int kv = (bh >> 2) & 3;
    const int h = bh & 15;                 // kv*4 + g

    const float scale = 0.08838834764831845f;  // 128^-0.5

    // --- load Q tile (64 x 128), transposed + scaled ---
    {
        const size_t qbase = ((size_t)(b * 2048 + t0)) * CDIM + h * 128;
#pragma unroll
        for (int it = 0; it < 8; it++) {
            int f = tid + it * 256;        // float4 index, 2048 total
            int r = f >> 5;                // row 0..63
            int c4 = f & 31;
            float4 val = *(const float4*)(q + qbase + (size_t)r * CDIM + c4 * 4);
            int d = c4 * 4;
            Qs[(d + 0) * QK_LD + r] = val.x * scale;
            Qs[(d + 1) * QK_LD + r] = val.y * scale;
            Qs[(d + 2) * QK_LD + r] = val.z * scale;
            Qs[(d + 3) * QK_LD + r] = val.w * scale;
        }
    }

    float m_i[4], l_i[4], accO[4][8];
#pragma unroll
    for (int i = 0; i < 4; i++) {
        m_i[i] = -INFINITY;
        l_i[i] = 0.0f;
#pragma unroll
        for (int j = 0; j < 8; j++) accO[i][j] = 0.0f;
    }

    for (int s0 = 0; s0 < 2048; s0 += 64) {
        __syncthreads();  // prev PV done (and Q load visible on first iter)

        // --- load K tile transposed ---
        {
            const size_t kbase = ((size_t)(b * 2048 + s0)) * KVDIM + kv * 128;
#pragma unroll
            for (int it = 0; it < 8; it++) {
                int f = tid + it * 256;
                int r = f >> 5;
                int c4 = f & 31;
                float4 val = *(const float4*)(k + kbase + (size_t)r * KVDIM + c4 * 4);
                int d = c4 * 4;
                KV[(d + 0) * QK_LD + r] = val.x;
                KV[(d + 1) * QK_LD + r] = val.y;
                KV[(d + 2) * QK_LD + r] = val.z;
                KV[(d + 3) * QK_LD + r] = val.w;
            }
        }
        __syncthreads();

        // --- S = (Q*scale) K^T, 64x64 tile, 4x4 per thread ---
        float accS[4][4];
#pragma unroll
        for (int i = 0; i < 4; i++)
#pragma unroll
            for (int j = 0; j < 4; j++) accS[i][j] = 0.0f;

#pragma unroll 4
        for (int d = 0; d < 128; d++) {
            float qv[4], kw[4];
            *(float4*)qv = *(const float4*)&Qs[d * QK_LD + ty * 4];
            *(float4*)kw = *(const float4*)&KV[d * QK_LD + tx * 4];
#pragma unroll
            for (int i = 0; i < 4; i++)
#pragma unroll
                for (int j = 0; j < 4; j++)
                    accS[i][j] += qv[i] * kw[j];
        }

        __syncthreads();  // all done reading K tile

        // --- load V tile (row-major) into same buffer ---
        {
            const size_t vbase = ((size_t)(b * 2048 + s0)) * KVDIM + kv * 128;
#pragma unroll
            for (int it = 0; it < 8; it++) {
                int f = tid + it * 256;
                int r = f >> 5;
                int c4 = f & 31;
                *(float4*)&KV[r * 128 + c4 * 4] =
                    *(const float4*)(v + vbase + (size_t)r * KVDIM + c4 * 4);
            }
        }

        // --- additive mask + online softmax (registers + Ps write) ---
#pragma unroll
        for (int i = 0; i < 4; i++) {
            int t = t0 + ty * 4 + i;
#pragma unroll
            for (int j = 0; j < 4; j++) {
                int s = s0 + tx * 4 + j;
                if (s <= t) accS[i][j] += 1.0f;   // reference ADDS tril(ones)
            }
            float rmax = fmaxf(fmaxf(accS[i][0], accS[i][1]),
                               fmaxf(accS[i][2], accS[i][3]));
#pragma unroll
            for (int off = 8; off > 0; off >>= 1)
                rmax = fmaxf(rmax, __shfl_xor_sync(0xffffffffu, rmax, off));
            float mnew = fmaxf(m_i[i], rmax);
            float fac = expf(m_i[i] - mnew);
            m_i[i] = mnew;
            float rsum = 0.0f;
#pragma unroll
            for (int j = 0; j < 4; j++) {
                float e = expf(accS[i][j] - mnew);
                Ps[(ty * 4 + i) * PS_LD + tx * 4 + j] = e;
                rsum += e;
            }
#pragma unroll
            for (int off = 8; off > 0; off >>= 1)
                rsum += __shfl_xor_sync(0xffffffffu, rsum, off);
            l_i[i] = l_i[i] * fac + rsum;
#pragma unroll
            for (int j = 0; j < 8; j++) accO[i][j] *= fac;
        }
        __syncthreads();  // V + Ps ready

        // --- O += P @ V  (4 rows x 8 cols per thread) ---
#pragma unroll 2
        for (int s = 0; s < 64; s++) {
            float p0 = Ps[(ty * 4 + 0) * PS_LD + s];
            float p1 = Ps[(ty * 4 + 1) * PS_LD + s];
            float p2 = Ps[(ty * 4 + 2) * PS_LD + s];
            float p3 = Ps[(ty * 4 + 3) * PS_LD + s];
            float va[8];
            *(float4*)(va)     = *(const float4*)&KV[s * 128 + tx * 4];
            *(float4*)(va + 4) = *(const float4*)&KV[s * 128 + 64 + tx * 4];
#pragma unroll
            for (int j = 0; j < 8; j++) {
                accO[0][j] += p0 * va[j];
                accO[1][j] += p1 * va[j];
                accO[2][j] += p2 * va[j];
                accO[3][j] += p3 * va[j];
            }
        }
    }

    // --- normalize and write out: layout [b][t][h*128 + d] ---
    const size_t obase = ((size_t)(b * 2048 + t0)) * CDIM + h * 128;
#pragma unroll
    for (int i = 0; i < 4; i++) {
        float inv = 1.0f / l_i[i];
        int tl = ty * 4 + i;
        float4 o0, o1;
        o0.x = accO[i][0] * inv; o0.y = accO[i][1] * inv;
        o0.z = accO[i][2] * inv; o0.w = accO[i][3] * inv;
        o1.x = accO[i][4] * inv; o1.y = accO[i][5] * inv;
        o1.z = accO[i][6] * inv; o1.w = accO[i][7] * inv;
        *(float4*)(o + obase + (size_t)tl * CDIM + tx * 4) = o0;
        *(float4*)(o + obase + (size_t)tl * CDIM + 64 + tx * 4) = o1;
    }
}

// ---------------------------------------------------------------------------
extern "C" void kernel_launch(void* const* d_in, const int* in_sizes, int n_in,
                              void* d_out, int out_size)
{
    const float* x  = (const float*)d_in[0];
    const float* wq = (const float*)d_in[1];
    const float* bq = (const float*)d_in[2];
    const float* wk = (const float*)d_in[3];
    const float* bk = (const float*)d_in[4];
    const float* wv = (const float*)d_in[5];
    const float* bv = (const float*)d_in[6];
    const float* wo = (const float*)d_in[7];
    const float* bo = (const float*)d_in[8];
    float* out = (float*)d_out;

    float *qp, *kp, *vp, *ap;
    cudaGetSymbolAddress((void**)&qp, g_q);
    cudaGetSymbolAddress((void**)&kp, g_k);
    cudaGetSymbolAddress((void**)&vp, g_v);
    cudaGetSymbolAddress((void**)&ap, g_att);

    // QKV projections
    gemm_nt<<<dim3(16, 32), 256>>>(x, wq, bq, qp, BT, CDIM, CDIM);
    gemm_nt<<<dim3(4, 32), 256>>>(x, wk, bk, kp, BT, KVDIM, CDIM);
    gemm_nt<<<dim3(4, 32), 256>>>(x, wv, bv, vp, BT, KVDIM, CDIM);

    // RoPE (head-indexed angles, per the reference's slicing bug)
    rope_kernel<<<(BT * 16 * 64 + 255) / 256, 256>>>(qp, 16);
    rope_kernel<<<(BT * 4 * 64 + 255) / 256, 256>>>(kp, 4);

    // Attention
    const int attn_smem = (2 * 128 * QK_LD + 64 * PS_LD) * (int)sizeof(float);
    cudaFuncSetAttribute(attn_kernel,
                         cudaFuncAttributeMaxDynamicSharedMemorySize, attn_smem);
    attn_kernel<<<dim3(32, 32), 256, attn_smem>>>(qp, kp, vp, ap);

    // Output projection -> d_out
    gemm_nt<<<dim3(16, 32), 256>>>(ap, wo, bo, out, BT, CDIM, CDIM);
}

// round 5
// speedup vs baseline: 1.3533x; 1.3533x over previous
#include <cuda_runtime.h>
#include <cuda_bf16.h>
#include <math.h>
#include <cstdint>

// Problem constants: B=2, T=2048, DIM=2048, H=16, KV=4, D=128, G=4
#define BT 4096
#define CDIM 2048
#define KVDIM 512

// Scratch (device globals; no allocation allowed)
__device__ float g_q[(size_t)BT * CDIM];
__device__ float g_k[(size_t)BT * KVDIM];
__device__ float g_v[(size_t)BT * KVDIM];
__device__ float g_att[(size_t)BT * CDIM];

// ---------------------------------------------------------------------------
// mma.sync m16n8k16 bf16 (sm_80-class; compiles at compute_100)
// ---------------------------------------------------------------------------
__device__ __forceinline__ void mma16816(
    float c[4], uint32_t a0, uint32_t a1, uint32_t a2, uint32_t a3,
    uint32_t b0, uint32_t b1)
{
    asm volatile(
        "mma.sync.aligned.m16n8k16.row.col.f32.bf16.bf16.f32 "
        "{%0,%1,%2,%3}, {%4,%5,%6,%7}, {%8,%9}, {%0,%1,%2,%3};"
        : "+f"(c[0]), "+f"(c[1]), "+f"(c[2]), "+f"(c[3])
        : "r"(a0), "r"(a1), "r"(a2), "r"(a3), "r"(b0), "r"(b1));
}

// split float4 into hi-bf16 pair-words and lo-bf16 pair-words
__device__ __forceinline__ void split4(float4 v, uint2& hi, uint2& lo) {
    __nv_bfloat16 hx = __float2bfloat16(v.x); float rx = v.x - __bfloat162float(hx);
    __nv_bfloat16 hy = __float2bfloat16(v.y); float ry = v.y - __bfloat162float(hy);
    __nv_bfloat16 hz = __float2bfloat16(v.z); float rz = v.z - __bfloat162float(hz);
    __nv_bfloat16 hw = __float2bfloat16(v.w); float rw = v.w - __bfloat162float(hw);
    hi.x = (uint32_t)__bfloat16_as_ushort(hx) | ((uint32_t)__bfloat16_as_ushort(hy) << 16);
    hi.y = (uint32_t)__bfloat16_as_ushort(hz) | ((uint32_t)__bfloat16_as_ushort(hw) << 16);
    lo.x = (uint32_t)__bfloat16_as_ushort(__float2bfloat16(rx))
         | ((uint32_t)__bfloat16_as_ushort(__float2bfloat16(ry)) << 16);
    lo.y = (uint32_t)__bfloat16_as_ushort(__float2bfloat16(rz))
         | ((uint32_t)__bfloat16_as_ushort(__float2bfloat16(rw)) << 16);
}

// swizzled word index inside a [128 rows x 32 words] tile (128B rows)
__device__ __forceinline__ uint32_t swz(uint32_t r, uint32_t w) {
    return r * 32u + (w ^ ((r & 7u) << 2));
}

// ===========================================================================
// mma.sync bf16 split-3-pass NT GEMM: C[M,N] = A[M,K]*B[N,K]^T + bias[N]
// CTA 128x128, 8 warps (2x4), warp tile 64x32.
// K chunk = 32 floats. Row layout: words 0-15 = hi bf16, words 16-31 = lo.
// Per chunk: 3 passes (Ah*Bh, Ah*Bl, Al*Bh) x 2 k16-steps.
// Double-buffered smem: 2 * (16KB A + 16KB B).
// ===========================================================================
#define GEMM_SMEM (4 * 16384)

__global__ __launch_bounds__(256) void gemm_mma(
    const float* __restrict__ A, const float* __restrict__ B,
    const float* __restrict__ bias, float* __restrict__ C,
    int M, int N, int K)
{
    extern __shared__ uint32_t smw[];   // [2][ A:4096 words | B:4096 words ]

    const int tid = threadIdx.x;
    const int wid = tid >> 5;
    const int lane = tid & 31;
    const int bm = blockIdx.y * 128;
    const int bn = blockIdx.x * 128;

    const int wm = wid >> 2;            // 0..1  (M)
    const int wn = wid & 3;             // 0..3  (N)

    // global load mapping: thread -> rows r0+32i, float4-col c4
    const int r0 = tid >> 3;            // 0..31
    const int c4 = tid & 7;             // 0..7
    const float* Ag = A + (size_t)(bm + r0) * K + c4 * 4;
    const float* Bg = B + (size_t)(bn + r0) * K + c4 * 4;
    const size_t strA = (size_t)32 * K;

    const int nchunk = K >> 5;

    float acc[4][4][4];
#pragma unroll
    for (int mt = 0; mt < 4; mt++)
#pragma unroll
        for (int nt = 0; nt < 4; nt++)
#pragma unroll
            for (int e = 0; e < 4; e++) acc[mt][nt][e] = 0.0f;

    float4 ra[4], rb[4];
#pragma unroll
    for (int i = 0; i < 4; i++) {
        ra[i] = *(const float4*)(Ag + i * strA);
        rb[i] = *(const float4*)(Bg + i * strA);
    }
    // store chunk 0 into stage 0
    {
        uint32_t* As = smw;
        uint32_t* Bs = smw + 4096;
#pragma unroll
        for (int i = 0; i < 4; i++) {
            uint32_t r = r0 + i * 32;
            uint2 hi, lo;
            split4(ra[i], hi, lo);
            *(uint2*)(As + swz(r, c4 * 2))       = hi;
            *(uint2*)(As + swz(r, 16 + c4 * 2))  = lo;
            split4(rb[i], hi, lo);
            *(uint2*)(Bs + swz(r, c4 * 2))       = hi;
            *(uint2*)(Bs + swz(r, 16 + c4 * 2))  = lo;
        }
    }

    const int lr = lane >> 2;           // 0..7
    const int lw = lane & 3;            // 0..3

    for (int c = 0; c < nchunk; ++c) {
        // prefetch next chunk
        if (c + 1 < nchunk) {
#pragma unroll
            for (int i = 0; i < 4; i++) {
                ra[i] = *(const float4*)(Ag + (c + 1) * 32 + i * strA);
                rb[i] = *(const float4*)(Bg + (c + 1) * 32 + i * strA);
            }
        }
        __syncthreads();

        uint32_t* As = smw + (c & 1) * 8192;
        uint32_t* Bs = As + 4096;

        // 3 passes: (Ah,Bh), (Ah,Bl), (Al,Bh); each pass 2 k16-steps
#pragma unroll
        for (int pass = 0; pass < 3; pass++) {
            const uint32_t aoff = (pass == 2) ? 16u : 0u;
            const uint32_t boff = (pass == 1) ? 16u : 0u;
#pragma unroll
            for (int s = 0; s < 2; s++) {
                const uint32_t kwa = aoff + s * 8 + lw;
                const uint32_t kwb = boff + s * 8 + lw;
                uint32_t bfr[4][2];
#pragma unroll
                for (int nt = 0; nt < 4; nt++) {
                    uint32_t n = wn * 32 + nt * 8 + lr;
                    bfr[nt][0] = Bs[swz(n, kwb)];
                    bfr[nt][1] = Bs[swz(n, kwb + 4)];
                }
#pragma unroll
                for (int mt = 0; mt < 4; mt++) {
                    uint32_t rrow = wm * 64 + mt * 16 + lr;
                    uint32_t a0 = As[swz(rrow, kwa)];
                    uint32_t a1 = As[swz(rrow + 8, kwa)];
                    uint32_t a2 = As[swz(rrow, kwa + 4)];
                    uint32_t a3 = As[swz(rrow + 8, kwa + 4)];
#pragma unroll
                    for (int nt = 0; nt < 4; nt++)
                        mma16816(acc[mt][nt], a0, a1, a2, a3,
                                 bfr[nt][0], bfr[nt][1]);
                }
            }
        }

        // store next chunk into other stage
        if (c + 1 < nchunk) {
            uint32_t* An = smw + ((c + 1) & 1) * 8192;
            uint32_t* Bn = An + 4096;
#pragma unroll
            for (int i = 0; i < 4; i++) {
                uint32_t r = r0 + i * 32;
                uint2 hi, lo;
                split4(ra[i], hi, lo);
                *(uint2*)(An + swz(r, c4 * 2))       = hi;
                *(uint2*)(An + swz(r, 16 + c4 * 2))  = lo;
                split4(rb[i], hi, lo);
                *(uint2*)(Bn + swz(r, c4 * 2))       = hi;
                *(uint2*)(Bn + swz(r, 16 + c4 * 2))  = lo;
            }
        }
    }

    // epilogue: acc -> gmem (+bias). c0,c1 at (row, col..col+1); c2,c3 row+8.
#pragma unroll
    for (int mt = 0; mt < 4; mt++) {
        int row = bm + wm * 64 + mt * 16 + lr;
#pragma unroll
        for (int nt = 0; nt < 4; nt++) {
            int col = bn + wn * 32 + nt * 8 + lw * 2;
            float b0 = bias[col], b1 = bias[col + 1];
            float2 v0 = make_float2(acc[mt][nt][0] + b0, acc[mt][nt][1] + b1);
            float2 v1 = make_float2(acc[mt][nt][2] + b0, acc[mt][nt][3] + b1);
            *(float2*)(C + (size_t)row * N + col) = v0;
            *(float2*)(C + (size_t)(row + 8) * N + col) = v1;
        }
    }
}

// ---------------------------------------------------------------------------
// RoPE (head-indexed angles per the reference's slicing quirk)
// ---------------------------------------------------------------------------
__global__ void rope_kernel(float* __restrict__ data, int heads)
{
    int idx = blockIdx.x * blockDim.x + threadIdx.x;
    int total = BT * heads * 64;
    if (idx >= total) return;
    int d = idx & 63;
    int h = (idx >> 6) % heads;
    int row = idx / (heads * 64);

    float invf = powf(10000.0f, -(float)d / 64.0f);
    float ang = (float)h * invf;
    float c = cosf(ang);
    float s = sinf(ang);

    float* p = data + (size_t)row * heads * 128 + h * 128;
    float x1 = p[d];
    float x2 = p[d + 64];
    p[d]      = x1 * c - x2 * s;
    p[d + 64] = x2 * c + x1 * s;
}

// ---------------------------------------------------------------------------
// Flash-style attention (additive mask per reference), fp32 SIMT.
// Identical to the Round-1 passing version (expf -> __expf).
// ---------------------------------------------------------------------------
#define QK_LD 68
#define PS_LD 68

__global__ __launch_bounds__(256) void attn_kernel(
    const float* __restrict__ q, const float* __restrict__ k,
    const float* __restrict__ v, float* __restrict__ o)
{
    extern __shared__ float smf[];
    float* Qs = smf;
    float* KV = smf + 128 * QK_LD;
    float* Ps = smf + 2 * 128 * QK_LD;

    const int tid = threadIdx.x;
    const int tx = tid & 15;
    const int ty = tid >> 4;
    const int t0 = blockIdx.x * 64;
    const int bh = blockIdx.y;
    const int b = bh >> 4;
    const int kv = (bh >> 2) & 3;
    const int h = bh & 15;

    const float scale = 0.08838834764831845f;

    {
        const size_t qbase = ((size_t)(b * 2048 + t0)) * CDIM + h * 128;
#pragma unroll
        for (int it = 0; it < 8; it++) {
            int f = tid + it * 256;
            int r = f >> 5;
            int c4v = f & 31;
            float4 val = *(const float4*)(q + qbase + (size_t)r * CDIM + c4v * 4);
            int d = c4v * 4;
            Qs[(d + 0) * QK_LD + r] = val.x * scale;
            Qs[(d + 1) * QK_LD + r] = val.y * scale;
            Qs[(d + 2) * QK_LD + r] = val.z * scale;
            Qs[(d + 3) * QK_LD + r] = val.w * scale;
        }
    }

    float m_i[4], l_i[4], accO[4][8];
#pragma unroll
    for (int i = 0; i < 4; i++) {
        m_i[i] = -INFINITY;
        l_i[i] = 0.0f;
#pragma unroll
        for (int j = 0; j < 8; j++) accO[i][j] = 0.0f;
    }

    for (int s0 = 0; s0 < 2048; s0 += 64) {
        __syncthreads();
        {
            const size_t kbase = ((size_t)(b * 2048 + s0)) * KVDIM + kv * 128;
#pragma unroll
            for (int it = 0; it < 8; it++) {
                int f = tid + it * 256;
                int r = f >> 5;
                int c4v = f & 31;
                float4 val = *(const float4*)(k + kbase + (size_t)r * KVDIM + c4v * 4);
                int d = c4v * 4;
                KV[(d + 0) * QK_LD + r] = val.x;
                KV[(d + 1) * QK_LD + r] = val.y;
                KV[(d + 2) * QK_LD + r] = val.z;
                KV[(d + 3) * QK_LD + r] = val.w;
            }
        }
        __syncthreads();

        float accS[4][4];
#pragma unroll
        for (int i = 0; i < 4; i++)
#pragma unroll
            for (int j = 0; j < 4; j++) accS[i][j] = 0.0f;

#pragma unroll 4
        for (int d = 0; d < 128; d++) {
            float qv[4], kw[4];
            *(float4*)qv = *(const float4*)&Qs[d * QK_LD + ty * 4];
            *(float4*)kw = *(const float4*)&KV[d * QK_LD + tx * 4];
#pragma unroll
            for (int i = 0; i < 4; i++)
#pragma unroll
                for (int j = 0; j < 4; j++)
                    accS[i][j] += qv[i] * kw[j];
        }

        __syncthreads();

        {
            const size_t vbase = ((size_t)(b * 2048 + s0)) * KVDIM + kv * 128;
#pragma unroll
            for (int it = 0; it < 8; it++) {
                int f = tid + it * 256;
                int r = f >> 5;
                int c4v = f & 31;
                *(float4*)&KV[r * 128 + c4v * 4] =
                    *(const float4*)(v + vbase + (size_t)r * KVDIM + c4v * 4);
            }
        }

#pragma unroll
        for (int i = 0; i < 4; i++) {
            int t = t0 + ty * 4 + i;
#pragma unroll
            for (int j = 0; j < 4; j++) {
                int s = s0 + tx * 4 + j;
                if (s <= t) accS[i][j] += 1.0f;
            }
            float rmax = fmaxf(fmaxf(accS[i][0], accS[i][1]),
                               fmaxf(accS[i][2], accS[i][3]));
#pragma unroll
            for (int off = 8; off > 0; off >>= 1)
                rmax = fmaxf(rmax, __shfl_xor_sync(0xffffffffu, rmax, off));
            float mnew = fmaxf(m_i[i], rmax);
            float fac = __expf(m_i[i] - mnew);
            m_i[i] = mnew;
            float rsum = 0.0f;
#pragma unroll
            for (int j = 0; j < 4; j++) {
                float e = __expf(accS[i][j] - mnew);
                Ps[(ty * 4 + i) * PS_LD + tx * 4 + j] = e;
                rsum += e;
            }
#pragma unroll
            for (int off = 8; off > 0; off >>= 1)
                rsum += __shfl_xor_sync(0xffffffffu, rsum, off);
            l_i[i] = l_i[i] * fac + rsum;
#pragma unroll
            for (int j = 0; j < 8; j++) accO[i][j] *= fac;
        }
        __syncthreads();

#pragma unroll 2
        for (int s = 0; s < 64; s++) {
            float p0 = Ps[(ty * 4 + 0) * PS_LD + s];
            float p1 = Ps[(ty * 4 + 1) * PS_LD + s];
            float p2 = Ps[(ty * 4 + 2) * PS_LD + s];
            float p3 = Ps[(ty * 4 + 3) * PS_LD + s];
            float va[8];
            *(float4*)(va)     = *(const float4*)&KV[s * 128 + tx * 4];
            *(float4*)(va + 4) = *(const float4*)&KV[s * 128 + 64 + tx * 4];
#pragma unroll
            for (int j = 0; j < 8; j++) {
                accO[0][j] += p0 * va[j];
                accO[1][j] += p1 * va[j];
                accO[2][j] += p2 * va[j];
                accO[3][j] += p3 * va[j];
            }
        }
    }

    const size_t obase = ((size_t)(b * 2048 + t0)) * CDIM + h * 128;
#pragma unroll
    for (int i = 0; i < 4; i++) {
        float inv = 1.0f / l_i[i];
        int tl = ty * 4 + i;
        float4 o0, o1;
        o0.x = accO[i][0] * inv; o0.y = accO[i][1] * inv;
        o0.z = accO[i][2] * inv; o0.w = accO[i][3] * inv;
        o1.x = accO[i][4] * inv; o1.y = accO[i][5] * inv;
        o1.z = accO[i][6] * inv; o1.w = accO[i][7] * inv;
        *(float4*)(o + obase + (size_t)tl * CDIM + tx * 4) = o0;
        *(float4*)(o + obase + (size_t)tl * CDIM + 64 + tx * 4) = o1;
    }
}

// ---------------------------------------------------------------------------
extern "C" void kernel_launch(void* const* d_in, const int* in_sizes, int n_in,
                              void* d_out, int out_size)
{
    const float* x  = (const float*)d_in[0];
    const float* wq = (const float*)d_in[1];
    const float* bq = (const float*)d_in[2];
    const float* wk = (const float*)d_in[3];
    const float* bk = (const float*)d_in[4];
    const float* wv = (const float*)d_in[5];
    const float* bv = (const float*)d_in[6];
    const float* wo = (const float*)d_in[7];
    const float* bo = (const float*)d_in[8];
    float* out = (float*)d_out;

    float *qp, *kp, *vp, *ap;
    cudaGetSymbolAddress((void**)&qp, g_q);
    cudaGetSymbolAddress((void**)&kp, g_k);
    cudaGetSymbolAddress((void**)&vp, g_v);
    cudaGetSymbolAddress((void**)&ap, g_att);

    cudaFuncSetAttribute(gemm_mma,
                         cudaFuncAttributeMaxDynamicSharedMemorySize, GEMM_SMEM);

    // QKV projections (mma.sync bf16 3-pass split)
    gemm_mma<<<dim3(16, 32), 256, GEMM_SMEM>>>(x, wq, bq, qp, BT, CDIM, CDIM);
    gemm_mma<<<dim3(4, 32), 256, GEMM_SMEM>>>(x, wk, bk, kp, BT, KVDIM, CDIM);
    gemm_mma<<<dim3(4, 32), 256, GEMM_SMEM>>>(x, wv, bv, vp, BT, KVDIM, CDIM);

    // RoPE
    rope_kernel<<<(BT * 16 * 64 + 255) / 256, 256>>>(qp, 16);
    rope_kernel<<<(BT * 4 * 64 + 255) / 256, 256>>>(kp, 4);

    // Attention
    const int attn_smem = (2 * 128 * QK_LD + 64 * PS_LD) * (int)sizeof(float);
    cudaFuncSetAttribute(attn_kernel,
                         cudaFuncAttributeMaxDynamicSharedMemorySize, attn_smem);
    attn_kernel<<<dim3(32, 32), 256, attn_smem>>>(qp, kp, vp, ap);

    // Output projection
    gemm_mma<<<dim3(16, 32), 256, GEMM_SMEM>>>(ap, wo, bo, out, BT, CDIM, CDIM);
}